// round 8
// baseline (speedup 1.0000x reference)
#include <cuda_runtime.h>
#include <cuda_bf16.h>
#include <math.h>
#include <stdint.h>
#include <mma.h>

using namespace nvcuda;

#define NN 100000
#define NP 100096
#define EE 600000
#define DD 128
#define SS 3
#define GG 64
#define OUTD 2
#define NPS (SS * NP)
#define MT2 256
#define M_TILES2 (NP / MT2)          // 391

// ---------------- device scratch ----------------
__device__ float g_x[NP * DD];
__device__ __nv_bfloat16 g_xb[NP * DD];
__device__ float g_h[NP * DD];
__device__ __nv_bfloat16 g_hb[NP * DD];
__device__ __nv_bfloat16 g_aggb[NP * DD];
__device__ float g_acc[NP * DD];
__device__ __nv_bfloat16 g_gh[NP * 3 * DD];
__device__ __nv_bfloat16 g_gi[NP * 3 * DD];
__device__ __nv_bfloat16 g_wcb[SS * 2 * 512 * DD];    // padded to 512 rows per (s,i)
__device__ __nv_bfloat16 g_wihb[SS * 512 * DD];       // padded to 512 rows per s
__device__ __nv_bfloat16 g_whhb[SS * 3 * DD * DD];
__device__ __nv_bfloat16 g_Wb[SS * 2 * DD * DD];
__device__ float g_pool[GG * DD];
__device__ float g_cnt[GG];
__device__ int   g_bsrc[EE];
__device__ int   g_ecnt[NPS];
__device__ int   g_ecur[NPS];
__device__ int   g_eoff[NPS + 1];

// ---------------- tiny utils ----------------
__global__ void zero_kernel(float* __restrict__ p, int n4) {
    int i = blockIdx.x * blockDim.x + threadIdx.x;
    if (i < n4) ((float4*)p)[i] = make_float4(0.f, 0.f, 0.f, 0.f);
}
__global__ void copy_pad_kernel(const float* __restrict__ x, float* __restrict__ xp,
                                __nv_bfloat16* __restrict__ xb,
                                __nv_bfloat16* __restrict__ hb) {
    int i = blockIdx.x * blockDim.x + threadIdx.x;
    if (i >= NP * 32) return;
    int n = i >> 5;
    float4 v = make_float4(0.f, 0.f, 0.f, 0.f);
    if (n < NN) {
        v = ((const float4*)x)[i];
    } else {
        *(__nv_bfloat162*)(hb + (size_t)i * 4)     = __floats2bfloat162_rn(0.f, 0.f);
        *(__nv_bfloat162*)(hb + (size_t)i * 4 + 2) = __floats2bfloat162_rn(0.f, 0.f);
    }
    ((float4*)xp)[(size_t)i] = v;
    *(__nv_bfloat162*)(xb + (size_t)i * 4)     = __floats2bfloat162_rn(v.x, v.y);
    *(__nv_bfloat162*)(xb + (size_t)i * 4 + 2) = __floats2bfloat162_rn(v.z, v.w);
}
__global__ void cvt_bf16_kernel(const float* __restrict__ src,
                                __nv_bfloat16* __restrict__ dst, int n4) {
    int i = blockIdx.x * blockDim.x + threadIdx.x;
    if (i >= n4) return;
    float4 v = ((const float4*)src)[i];
    *(__nv_bfloat162*)(dst + (size_t)i * 4)     = __floats2bfloat162_rn(v.x, v.y);
    *(__nv_bfloat162*)(dst + (size_t)i * 4 + 2) = __floats2bfloat162_rn(v.z, v.w);
}
__global__ void zero2_ints(int* __restrict__ a, int* __restrict__ b, int n) {
    int i = blockIdx.x * blockDim.x + threadIdx.x;
    if (i < n) { a[i] = 0; b[i] = 0; }
}

// ---------------- CSR build ----------------
__global__ void ecount_kernel(const int* __restrict__ dst, const int* __restrict__ attr,
                              int* __restrict__ cnt, int E) {
    int e = blockIdx.x * blockDim.x + threadIdx.x;
    if (e < E) atomicAdd(&cnt[attr[e] * NP + dst[e]], 1);
}
__global__ void scan_kernel(const int* __restrict__ cnt, int* __restrict__ off, int n) {
    __shared__ int ssum[1024];
    int t = threadIdx.x;
    int per = (n + 1023) / 1024;
    int b0 = t * per;
    int b1 = b0 + per; if (b1 > n) b1 = n; if (b0 > n) b0 = n;
    int s = 0;
    for (int i = b0; i < b1; i++) s += cnt[i];
    ssum[t] = s;
    __syncthreads();
    for (int d = 1; d < 1024; d <<= 1) {
        int v = (t >= d) ? ssum[t - d] : 0;
        __syncthreads();
        ssum[t] += v;
        __syncthreads();
    }
    int run = (t == 0) ? 0 : ssum[t - 1];
    if (t == 1023) off[n] = ssum[1023];
    for (int i = b0; i < b1; i++) { off[i] = run; run += cnt[i]; }
}
__global__ void fill_kernel(const int* __restrict__ src, const int* __restrict__ dst,
                            const int* __restrict__ attr, const int* __restrict__ off,
                            int* __restrict__ cur, int* __restrict__ bsrc, int E) {
    int e = blockIdx.x * blockDim.x + threadIdx.x;
    if (e >= E) return;
    int idx = attr[e] * NP + dst[e];
    int pos = off[idx] + atomicAdd(&cur[idx], 1);
    bsrc[pos] = src[e];
}

// ---------------- gather (bf16): agg[n] = mean of feat[src] ----------
__global__ void gather_kernel(const int* __restrict__ off, const int* __restrict__ bsrc,
                              int s, const __nv_bfloat16* __restrict__ feat,
                              __nv_bfloat16* __restrict__ agg) {
    int w = (blockIdx.x * blockDim.x + threadIdx.x) >> 5;
    int lane = threadIdx.x & 31;
    if (w >= NP) return;
    int idx = s * NP + w;
    int e0 = off[idx], e1 = off[idx + 1];
    float a0 = 0.f, a1 = 0.f, a2 = 0.f, a3 = 0.f;
    for (int e = e0; e < e1; e++) {
        int sn = bsrc[e];
        uint2 u = *(const uint2*)(feat + (size_t)sn * DD + lane * 4);
        __nv_bfloat162 p0 = *(__nv_bfloat162*)&u.x;
        __nv_bfloat162 p1 = *(__nv_bfloat162*)&u.y;
        float2 f0 = __bfloat1622float2(p0), f1 = __bfloat1622float2(p1);
        a0 += f0.x; a1 += f0.y; a2 += f1.x; a3 += f1.y;
    }
    if (e1 > e0) {
        float inv = 1.0f / (float)(e1 - e0);
        a0 *= inv; a1 *= inv; a2 *= inv; a3 *= inv;
    }
    uint2 o;
    *(__nv_bfloat162*)&o.x = __floats2bfloat162_rn(a0, a1);
    *(__nv_bfloat162*)&o.y = __floats2bfloat162_rn(a2, a3);
    *(uint2*)(agg + (size_t)w * DD + lane * 4) = o;
}

// ================= streaming bf16 WMMA GEMM (256x128 CTA, 64x64 warp) ========
#define LDTB 136
#define LDC2 132
#define SMB_B 34816                      // 128 x 136 bf16
#define SMB_A 69632                      // 256 x 136 bf16
#define BG_SMEM (SMB_B + 2 * SMB_A)      // 174080

__device__ __forceinline__ void cp16(void* s, const void* g) {
    uint32_t sa = (uint32_t)__cvta_generic_to_shared(s);
    asm volatile("cp.async.cg.shared.global [%0], [%1], 16;" :: "r"(sa), "l"(g));
}
__device__ __forceinline__ void tile_load_async(__nv_bfloat16* dstS,
                                                const __nv_bfloat16* srcG,
                                                int rows, int tid) {
    for (int slot = tid; slot < rows * 16; slot += 256) {
        int r = slot >> 4;
        int c8 = (slot & 15) * 8;
        cp16(dstS + r * LDTB + c8, srcG + (size_t)r * 128 + c8);
    }
}

__global__ void __launch_bounds__(256, 1)
bf16_gemm(const __nv_bfloat16* __restrict__ A0, const __nv_bfloat16* __restrict__ B0,
          const float* __restrict__ bias0, void* __restrict__ C0v,
          const __nv_bfloat16* __restrict__ A1, const __nv_bfloat16* __restrict__ B1,
          const float* __restrict__ bias1, void* __restrict__ C1v,
          int J, int out_bf16, int mtiles, size_t sA, size_t sB, size_t sC) {
    const __nv_bfloat16 *A, *B;
    const float* bias;
    void* C;
    if (A1 != nullptr) {
        if (blockIdx.z == 0) { A = A0; B = B0; bias = bias0; C = C0v; }
        else                 { A = A1; B = B1; bias = bias1; C = C1v; }
    } else {
        A = A0 + (size_t)blockIdx.z * sA;
        B = B0 + (size_t)blockIdx.z * sB;
        bias = bias0;
        C = (void*)((__nv_bfloat16*)C0v + (size_t)blockIdx.z * sC * (out_bf16 ? 1 : 2));
    }

    extern __shared__ char smx[];
    __nv_bfloat16* Bs = (__nv_bfloat16*)smx;
    __nv_bfloat16* Abuf0 = (__nv_bfloat16*)(smx + SMB_B);
    __nv_bfloat16* Abuf1 = (__nv_bfloat16*)(smx + SMB_B + SMB_A);

    int tid = threadIdx.x;
    int warp = tid >> 5;
    int row0 = (warp >> 1) * 64;      // 4 row bands of 64
    int col0 = (warp & 1) * 64;       // 2 col bands of 64
    int bn = blockIdx.x * 128;

    int mt = blockIdx.y;
    if (mt >= mtiles) return;

    tile_load_async(Bs, B + (size_t)bn * 128, 128, tid);
    tile_load_async(Abuf0, A + (size_t)mt * MT2 * 128, MT2, tid);
    asm volatile("cp.async.commit_group;");

    int buf = 0;
    while (mt < mtiles) {
        int nxt = mt + gridDim.y;
        bool pf = (nxt < mtiles);
        __nv_bfloat16* Acur = buf ? Abuf1 : Abuf0;
        __nv_bfloat16* Aalt = buf ? Abuf0 : Abuf1;
        if (pf) {
            tile_load_async(Aalt, A + (size_t)nxt * MT2 * 128, MT2, tid);
            asm volatile("cp.async.commit_group;");
            asm volatile("cp.async.wait_group 1;");
        } else {
            asm volatile("cp.async.wait_group 0;");
        }
        __syncthreads();

        wmma::fragment<wmma::accumulator, 16, 16, 16, float> acc[4][4];
#pragma unroll
        for (int i = 0; i < 4; i++)
#pragma unroll
            for (int j = 0; j < 4; j++) wmma::fill_fragment(acc[i][j], 0.0f);

#pragma unroll
        for (int k = 0; k < 8; k++) {
            wmma::fragment<wmma::matrix_a, 16, 16, 16, __nv_bfloat16, wmma::row_major> a[4];
            wmma::fragment<wmma::matrix_b, 16, 16, 16, __nv_bfloat16, wmma::col_major> b[4];
#pragma unroll
            for (int i = 0; i < 4; i++)
                wmma::load_matrix_sync(a[i], Acur + (row0 + i * 16) * LDTB + k * 16, LDTB);
#pragma unroll
            for (int j = 0; j < 4; j++)
                wmma::load_matrix_sync(b[j], Bs + (col0 + j * 16) * LDTB + k * 16, LDTB);
#pragma unroll
            for (int i = 0; i < 4; i++)
#pragma unroll
                for (int j = 0; j < 4; j++)
                    wmma::mma_sync(acc[i][j], a[i], b[j], acc[i][j]);
        }
        __syncthreads();

        // epilogue: two 128-row halves staged in the just-consumed A buffer
        float* Cs = (float*)Acur;
        int bm = mt * MT2;
#pragma unroll
        for (int h = 0; h < 2; h++) {
            if ((row0 >> 7) == h) {
                int lr = row0 & 127;
#pragma unroll
                for (int i = 0; i < 4; i++)
#pragma unroll
                    for (int j = 0; j < 4; j++)
                        wmma::store_matrix_sync(Cs + (lr + i * 16) * LDC2 + col0 + j * 16,
                                                acc[i][j], LDC2, wmma::mem_row_major);
            }
            __syncthreads();
            for (int slot = tid; slot < 128 * 32; slot += 256) {
                int r = slot >> 5;
                int c4 = (slot & 31) * 4;
                float4 v = *(float4*)(Cs + r * LDC2 + c4);
                if (bias != nullptr) {
                    v.x += bias[bn + c4 + 0];
                    v.y += bias[bn + c4 + 1];
                    v.z += bias[bn + c4 + 2];
                    v.w += bias[bn + c4 + 3];
                }
                int grow = bm + h * 128 + r;
                if (out_bf16) {
                    __nv_bfloat16* crow = (__nv_bfloat16*)C + (size_t)grow * J + bn + c4;
                    *(__nv_bfloat162*)(crow)     = __floats2bfloat162_rn(v.x, v.y);
                    *(__nv_bfloat162*)(crow + 2) = __floats2bfloat162_rn(v.z, v.w);
                } else {
                    *(float4*)((float*)C + (size_t)grow * J + bn + c4) = v;
                }
            }
            __syncthreads();
        }
        mt = nxt;
        buf ^= 1;
    }
}

// ---------------- GRU elementwise combine (tanh.approx) ----------------
__device__ __forceinline__ float tanhapx(float x) {
    float y;
    asm("tanh.approx.f32 %0, %1;" : "=f"(y) : "f"(x));
    return y;
}
__device__ __forceinline__ float sigf(float x) {
    return 0.5f * tanhapx(0.5f * x) + 0.5f;
}

__device__ __forceinline__ float4 ldbf4(const __nv_bfloat16* p) {
    uint2 u = *(const uint2*)p;
    __nv_bfloat162 a = *(__nv_bfloat162*)&u.x;
    __nv_bfloat162 b = *(__nv_bfloat162*)&u.y;
    float2 fa = __bfloat1622float2(a), fb = __bfloat1622float2(b);
    return make_float4(fa.x, fa.y, fb.x, fb.y);
}
__device__ __forceinline__ void stbf4(__nv_bfloat16* p, float4 v) {
    uint2 u;
    *(__nv_bfloat162*)&u.x = __floats2bfloat162_rn(v.x, v.y);
    *(__nv_bfloat162*)&u.y = __floats2bfloat162_rn(v.z, v.w);
    *(uint2*)p = u;
}

__global__ void gru_combine_kernel(const __nv_bfloat16* __restrict__ gi,
                                   const __nv_bfloat16* __restrict__ gh,
                                   const float* __restrict__ hold,
                                   float* __restrict__ hout,
                                   __nv_bfloat16* __restrict__ houtb,
                                   float* __restrict__ accb, int mode) {
    int idx = blockIdx.x * blockDim.x + threadIdx.x;
    if (idx >= NN * 32) return;
    int n = idx >> 5;
    int c = (idx & 31) * 4;
    const __nv_bfloat16* gir = gi + (size_t)n * 384;
    const __nv_bfloat16* ghr = gh + (size_t)n * 384;
    float4 ir = ldbf4(gir + c);
    float4 iz = ldbf4(gir + 128 + c);
    float4 in4 = ldbf4(gir + 256 + c);
    float4 hr = ldbf4(ghr + c);
    float4 hz = ldbf4(ghr + 128 + c);
    float4 hn = ldbf4(ghr + 256 + c);
    float4 h = *(const float4*)(hold + (size_t)n * 128 + c);
    float4 o;
    { float r = sigf(ir.x + hr.x), z = sigf(iz.x + hz.x);
      float nn = tanhapx(in4.x + r * hn.x); o.x = (1.f - z) * nn + z * h.x; }
    { float r = sigf(ir.y + hr.y), z = sigf(iz.y + hz.y);
      float nn = tanhapx(in4.y + r * hn.y); o.y = (1.f - z) * nn + z * h.y; }
    { float r = sigf(ir.z + hr.z), z = sigf(iz.z + hz.z);
      float nn = tanhapx(in4.z + r * hn.z); o.z = (1.f - z) * nn + z * h.z; }
    { float r = sigf(ir.w + hr.w), z = sigf(iz.w + hz.w);
      float nn = tanhapx(in4.w + r * hn.w); o.w = (1.f - z) * nn + z * h.w; }
    size_t p = (size_t)n * 128 + c;
    if (mode == 0) {
        *(float4*)(hout + p) = o;
        stbf4(houtb + p, o);
    } else if (mode == 1) {
        *(float4*)(accb + p) = o;
    } else if (mode == 2) {
        float4 av = *(float4*)(accb + p);
        av.x += o.x; av.y += o.y; av.z += o.z; av.w += o.w;
        *(float4*)(accb + p) = av;
    } else {
        float4 av = *(float4*)(accb + p);
        float4 xv;
        xv.x = (av.x + o.x) * (1.0f / 3.0f);
        xv.y = (av.y + o.y) * (1.0f / 3.0f);
        xv.z = (av.z + o.z) * (1.0f / 3.0f);
        xv.w = (av.w + o.w) * (1.0f / 3.0f);
        *(float4*)(hout + p) = xv;
        stbf4(houtb + p, xv);
    }
}

// ---------------- pooling / MLP ----------------
__global__ void cnt_kernel(const int* __restrict__ batch, float* __restrict__ cnt, int n) {
    int i = blockIdx.x * blockDim.x + threadIdx.x;
    if (i < n) atomicAdd(&cnt[batch[i]], 1.0f);
}
__global__ void pool_kernel(const float* __restrict__ x, const int* __restrict__ batch,
                            float* __restrict__ pool) {
    int idx = blockIdx.x * blockDim.x + threadIdx.x;
    if (idx >= NN * 32) return;
    int n = idx >> 5;
    int c = (idx & 31) * 4;
    int g = batch[n];
    float4 v = *(const float4*)(x + (size_t)n * 128 + c);
    float* o = pool + (size_t)g * 128 + c;
    asm volatile("red.global.add.v4.f32 [%0], {%1,%2,%3,%4};"
                 :: "l"(o), "f"(v.x), "f"(v.y), "f"(v.z), "f"(v.w) : "memory");
}
__global__ void mlp_kernel(const float* __restrict__ pool, const float* __restrict__ cnt,
                           const float* __restrict__ pt,
                           const float* __restrict__ fc1w, const float* __restrict__ fc1b,
                           const float* __restrict__ fc2w, const float* __restrict__ fc2b,
                           const float* __restrict__ fclw, const float* __restrict__ fclb,
                           float* __restrict__ out) {
    __shared__ float h1[GG * 80];
    __shared__ float h2[GG * 80];
    int tid = threadIdx.x;
    for (int t = tid; t < GG * 80; t += blockDim.x) {
        int g = t / 80, j = t - (t / 80) * 80;
        float ic = 1.0f / fmaxf(cnt[g], 1.0f);
        float acc = fc1b[j];
        const float* w = fc1w + j * 129;
        const float* p = pool + g * 128;
        for (int k = 0; k < 128; k++) acc = fmaf(p[k] * ic, w[k], acc);
        acc = fmaf(pt[g], w[128], acc);
        h1[t] = acc > 0.f ? acc : 0.01f * acc;
    }
    __syncthreads();
    for (int t = tid; t < GG * 80; t += blockDim.x) {
        int g = t / 80, j = t - (t / 80) * 80;
        float acc = fc2b[j];
        const float* w = fc2w + j * 80;
        const float* hh = h1 + g * 80;
        for (int k = 0; k < 80; k++) acc = fmaf(hh[k], w[k], acc);
        h2[t] = acc > 0.f ? acc : 0.01f * acc;
    }
    __syncthreads();
    for (int t = tid; t < GG * OUTD; t += blockDim.x) {
        int g = t / OUTD, o = t - (t / OUTD) * OUTD;
        float acc = fclb[o];
        const float* w = fclw + o * 80;
        const float* hh = h2 + g * 80;
        for (int k = 0; k < 80; k++) acc = fmaf(hh[k], w[k], acc);
        out[t] = acc;
    }
}

// ---------------- host launcher ----------------
extern "C" void kernel_launch(void* const* d_in, const int* in_sizes, int n_in,
                              void* d_out, int out_size) {
    (void)in_sizes; (void)n_in; (void)out_size;
    const float* x     = (const float*)d_in[0];
    const int*   eidx  = (const int*)d_in[1];
    const int*   eattr = (const int*)d_in[2];
    const int*   batch = (const int*)d_in[3];
    const float* pt    = (const float*)d_in[4];
    const float* W     = (const float*)d_in[5];
    const float* wih   = (const float*)d_in[6];
    const float* whh   = (const float*)d_in[7];
    const float* bih   = (const float*)d_in[8];
    const float* bhh   = (const float*)d_in[9];
    const float* fc1w  = (const float*)d_in[10];
    const float* fc1b  = (const float*)d_in[11];
    const float* fc2w  = (const float*)d_in[12];
    const float* fc2b  = (const float*)d_in[13];
    const float* fclw  = (const float*)d_in[14];
    const float* fclb  = (const float*)d_in[15];
    float* out = (float*)d_out;

    const int* src = eidx;
    const int* dst = eidx + EE;

    float *xp, *hp, *accp, *poolp, *cntp;
    __nv_bfloat16 *xb, *hb, *aggb, *ghp, *gip, *wcb, *wihb, *whhb, *Wb;
    int *bsrcp, *ecntp, *ecurp, *eoffp;
    cudaGetSymbolAddress((void**)&xp,    g_x);
    cudaGetSymbolAddress((void**)&xb,    g_xb);
    cudaGetSymbolAddress((void**)&hp,    g_h);
    cudaGetSymbolAddress((void**)&hb,    g_hb);
    cudaGetSymbolAddress((void**)&aggb,  g_aggb);
    cudaGetSymbolAddress((void**)&accp,  g_acc);
    cudaGetSymbolAddress((void**)&ghp,   g_gh);
    cudaGetSymbolAddress((void**)&gip,   g_gi);
    cudaGetSymbolAddress((void**)&wcb,   g_wcb);
    cudaGetSymbolAddress((void**)&wihb,  g_wihb);
    cudaGetSymbolAddress((void**)&whhb,  g_whhb);
    cudaGetSymbolAddress((void**)&Wb,    g_Wb);
    cudaGetSymbolAddress((void**)&poolp, g_pool);
    cudaGetSymbolAddress((void**)&cntp,  g_cnt);
    cudaGetSymbolAddress((void**)&bsrcp, g_bsrc);
    cudaGetSymbolAddress((void**)&ecntp, g_ecnt);
    cudaGetSymbolAddress((void**)&ecurp, g_ecur);
    cudaGetSymbolAddress((void**)&eoffp, g_eoff);

    cudaFuncSetAttribute(bf16_gemm, cudaFuncAttributeMaxDynamicSharedMemorySize, BG_SMEM);

    const int TB = 256;
    dim3 main_grid1(3, 49, 1);
    dim3 main_grid2(3, 24, 2);
    dim3 wc_grid(1, 2, 2);

    // 0: copy + pad + bf16 mirror
    copy_pad_kernel<<<(NP * 32 + TB - 1) / TB, TB>>>(x, xp, xb, hb);
    // 1: whh -> bf16
    cvt_bf16_kernel<<<(SS * 384 * 32 + TB - 1) / TB, TB>>>(whh, whhb, SS * 384 * 32);
    // 2: zero CSR arrays
    zero2_ints<<<(NPS + TB - 1) / TB, TB>>>(ecntp, ecurp, NPS);
    // 3 (PROFILED): gh GEMM for step (0,0,0)
    bf16_gemm<<<main_grid1, TB, BG_SMEM>>>(xb, whhb, bhh, ghp,
                                           nullptr, nullptr, nullptr, nullptr,
                                           384, 1, M_TILES2, 0, 0, 0);
    // wih -> bf16 with 512-row padded stride per s
    for (int s = 0; s < SS; s++)
        cvt_bf16_kernel<<<(384 * 32 + TB - 1) / TB, TB>>>(
            wih + (size_t)s * 384 * 128, wihb + (size_t)s * 512 * 128, 384 * 32);
    cvt_bf16_kernel<<<(SS * 2 * 128 * 32 + TB - 1) / TB, TB>>>(W, Wb, SS * 2 * 128 * 32);
    ecount_kernel<<<(EE + TB - 1) / TB, TB>>>(dst, eattr, ecntp, EE);
    scan_kernel<<<1, 1024>>>(ecntp, eoffp, NPS);
    fill_kernel<<<(EE + TB - 1) / TB, TB>>>(src, dst, eattr, eoffp, ecurp, bsrcp, EE);
    // combined weights Wc[s,i] = wih[s] @ W[s,i]  (bf16 out, padded 512-row blocks)
    for (int s = 0; s < SS; s++)
        bf16_gemm<<<wc_grid, TB, BG_SMEM>>>(
            wihb + (size_t)s * 512 * 128, Wb + (size_t)(s * 2) * 128 * 128, nullptr,
            wcb + (size_t)(s * 2) * 512 * 128,
            nullptr, nullptr, nullptr, nullptr,
            128, 1, 2, (size_t)0, (size_t)(128 * 128), (size_t)(512 * 128));

    // --- main GGNN loop ---
    for (int pass = 0; pass < 2; pass++) {
        for (int s = 0; s < SS; s++) {
            for (int i = 0; i < 2; i++) {
                const __nv_bfloat16* ain = (i == 0) ? xb : hb;
                const float* hold = (i == 0) ? xp : hp;
                const __nv_bfloat16* wc_si = wcb + (size_t)(s * 2 + i) * 512 * 128;
                gather_kernel<<<(NP * 32 + TB - 1) / TB, TB>>>(eoffp, bsrcp, s, ain, aggb);
                if (pass == 0 && s == 0 && i == 0) {
                    bf16_gemm<<<main_grid1, TB, BG_SMEM>>>(
                        aggb, wc_si, bih, gip,
                        nullptr, nullptr, nullptr, nullptr,
                        384, 1, M_TILES2, 0, 0, 0);
                } else {
                    bf16_gemm<<<main_grid2, TB, BG_SMEM>>>(
                        ain, whhb + (size_t)s * 384 * 128, bhh + s * 384, ghp,
                        aggb, wc_si, bih + s * 384, gip,
                        384, 1, M_TILES2, 0, 0, 0);
                }
                int mode = (i == 0) ? 0 : ((s == 0) ? 1 : ((s == 1) ? 2 : 3));
                gru_combine_kernel<<<(NN * 32 + TB - 1) / TB, TB>>>(
                    gip, ghp, hold, (mode == 3) ? xp : hp, (mode == 3) ? xb : hb,
                    accp, mode);
            }
        }
    }

    // --- pooling + MLP ---
    zero_kernel<<<(GG * DD / 4 + TB - 1) / TB, TB>>>(poolp, GG * DD / 4);
    zero_kernel<<<1, GG / 4>>>(cntp, GG / 4);
    cnt_kernel<<<(NN + TB - 1) / TB, TB>>>(batch, cntp, NN);
    pool_kernel<<<(NN * 32 + TB - 1) / TB, TB>>>(xp, batch, poolp);
    mlp_kernel<<<1, 256>>>(poolp, cntp, pt, fc1w, fc1b, fc2w, fc2b, fclw, fclb, out);
}

// round 9
// speedup vs baseline: 1.0176x; 1.0176x over previous
#include <cuda_runtime.h>
#include <cuda_bf16.h>
#include <math.h>
#include <stdint.h>
#include <mma.h>

using namespace nvcuda;

#define NN 100000
#define NP 100096
#define EE 600000
#define DD 128
#define SS 3
#define GG 64
#define OUTD 2
#define NPS (SS * NP)
#define M_TILES (NP / 128)        // 782

// ---------------- device scratch ----------------
__device__ float g_x[NP * DD];                    // fp32 x (pooling + final avg)
__device__ __nv_bfloat16 g_xb[NP * DD];           // bf16 x
__device__ __nv_bfloat16 g_hb3[SS * NP * DD];     // per-edge-set hidden, bf16
__device__ __nv_bfloat16 g_agg3[SS * NP * DD];    // gathered means
__device__ __nv_bfloat16 g_gi3[SS * NP * 3 * DD];
__device__ __nv_bfloat16 g_gh3[SS * NP * 3 * DD];
__device__ __nv_bfloat16 g_wcb[SS * 2 * 3 * DD * DD];
__device__ __nv_bfloat16 g_wihb[SS * 3 * DD * DD];
__device__ __nv_bfloat16 g_whhb[SS * 3 * DD * DD];
__device__ __nv_bfloat16 g_Wb[SS * 2 * DD * DD];
__device__ float g_pool[GG * DD];
__device__ float g_cnt[GG];
__device__ int   g_bsrc[EE];
__device__ int   g_ecnt[NPS];
__device__ int   g_ecur[NPS];
__device__ int   g_eoff[NPS + 1];

// ---------------- tiny utils ----------------
__global__ void zero_kernel(float* __restrict__ p, int n4) {
    int i = blockIdx.x * blockDim.x + threadIdx.x;
    if (i < n4) ((float4*)p)[i] = make_float4(0.f, 0.f, 0.f, 0.f);
}
__global__ void copy_pad_kernel(const float* __restrict__ x, float* __restrict__ xp,
                                __nv_bfloat16* __restrict__ xb) {
    int i = blockIdx.x * blockDim.x + threadIdx.x;
    if (i >= NP * 32) return;
    int n = i >> 5;
    float4 v = make_float4(0.f, 0.f, 0.f, 0.f);
    if (n < NN) v = ((const float4*)x)[i];
    ((float4*)xp)[(size_t)i] = v;
    *(__nv_bfloat162*)(xb + (size_t)i * 4)     = __floats2bfloat162_rn(v.x, v.y);
    *(__nv_bfloat162*)(xb + (size_t)i * 4 + 2) = __floats2bfloat162_rn(v.z, v.w);
}
__global__ void cvt_bf16_kernel(const float* __restrict__ src,
                                __nv_bfloat16* __restrict__ dst, int n4) {
    int i = blockIdx.x * blockDim.x + threadIdx.x;
    if (i >= n4) return;
    float4 v = ((const float4*)src)[i];
    *(__nv_bfloat162*)(dst + (size_t)i * 4)     = __floats2bfloat162_rn(v.x, v.y);
    *(__nv_bfloat162*)(dst + (size_t)i * 4 + 2) = __floats2bfloat162_rn(v.z, v.w);
}
__global__ void zero2_ints(int* __restrict__ a, int* __restrict__ b, int n) {
    int i = blockIdx.x * blockDim.x + threadIdx.x;
    if (i < n) { a[i] = 0; b[i] = 0; }
}

// ---------------- CSR build ----------------
__global__ void ecount_kernel(const int* __restrict__ dst, const int* __restrict__ attr,
                              int* __restrict__ cnt, int E) {
    int e = blockIdx.x * blockDim.x + threadIdx.x;
    if (e < E) atomicAdd(&cnt[attr[e] * NP + dst[e]], 1);
}
__global__ void scan_kernel(const int* __restrict__ cnt, int* __restrict__ off, int n) {
    __shared__ int ssum[1024];
    int t = threadIdx.x;
    int per = (n + 1023) / 1024;
    int b0 = t * per;
    int b1 = b0 + per; if (b1 > n) b1 = n; if (b0 > n) b0 = n;
    int s = 0;
    for (int i = b0; i < b1; i++) s += cnt[i];
    ssum[t] = s;
    __syncthreads();
    for (int d = 1; d < 1024; d <<= 1) {
        int v = (t >= d) ? ssum[t - d] : 0;
        __syncthreads();
        ssum[t] += v;
        __syncthreads();
    }
    int run = (t == 0) ? 0 : ssum[t - 1];
    if (t == 1023) off[n] = ssum[1023];
    for (int i = b0; i < b1; i++) { off[i] = run; run += cnt[i]; }
}
__global__ void fill_kernel(const int* __restrict__ src, const int* __restrict__ dst,
                            const int* __restrict__ attr, const int* __restrict__ off,
                            int* __restrict__ cur, int* __restrict__ bsrc, int E) {
    int e = blockIdx.x * blockDim.x + threadIdx.x;
    if (e >= E) return;
    int idx = attr[e] * NP + dst[e];
    int pos = off[idx] + atomicAdd(&cur[idx], 1);
    bsrc[pos] = src[e];
}

// ---------------- gather all 3 types ----------------
struct Feat3 { const __nv_bfloat16* p[3]; };

__global__ void gather3_kernel(const int* __restrict__ off, const int* __restrict__ bsrc,
                               Feat3 f, __nv_bfloat16* __restrict__ agg3) {
    int w = (blockIdx.x * blockDim.x + threadIdx.x) >> 5;
    int lane = threadIdx.x & 31;
    if (w >= SS * NP) return;
    int s = w / NP;
    const __nv_bfloat16* feat = f.p[s];
    int e0 = off[w], e1 = off[w + 1];
    float a0 = 0.f, a1 = 0.f, a2 = 0.f, a3 = 0.f;
    for (int e = e0; e < e1; e++) {
        int sn = bsrc[e];
        uint2 u = *(const uint2*)(feat + (size_t)sn * DD + lane * 4);
        __nv_bfloat162 p0 = *(__nv_bfloat162*)&u.x;
        __nv_bfloat162 p1 = *(__nv_bfloat162*)&u.y;
        float2 f0 = __bfloat1622float2(p0), f1 = __bfloat1622float2(p1);
        a0 += f0.x; a1 += f0.y; a2 += f1.x; a3 += f1.y;
    }
    if (e1 > e0) {
        float inv = 1.0f / (float)(e1 - e0);
        a0 *= inv; a1 *= inv; a2 *= inv; a3 *= inv;
    }
    uint2 o;
    *(__nv_bfloat162*)&o.x = __floats2bfloat162_rn(a0, a1);
    *(__nv_bfloat162*)&o.y = __floats2bfloat162_rn(a2, a3);
    *(uint2*)(agg3 + (size_t)w * DD + lane * 4) = o;
}

// ================= streaming bf16 WMMA GEMM (R7 core, 6-slice batched) =======
#define LDTB 136
#define LDC2 132
#define SMB 34816
#define BG_SMEM (3 * SMB)

struct GemmArgs {
    const __nv_bfloat16* A[6];
    const __nv_bfloat16* B[6];
    const float* bias[6];
    __nv_bfloat16* C[6];
};

__device__ __forceinline__ void cp16(void* s, const void* g) {
    uint32_t sa = (uint32_t)__cvta_generic_to_shared(s);
    asm volatile("cp.async.cg.shared.global [%0], [%1], 16;" :: "r"(sa), "l"(g));
}
__device__ __forceinline__ void tile_load_async(__nv_bfloat16* dstS,
                                                const __nv_bfloat16* srcG, int tid) {
    for (int slot = tid; slot < 2048; slot += 256) {
        int r = slot >> 4;
        int c8 = (slot & 15) * 8;
        cp16(dstS + r * LDTB + c8, srcG + (size_t)r * 128 + c8);
    }
}

__global__ void __launch_bounds__(256, 2)
bf16_gemm(GemmArgs ga, int J, int mtiles) {
    int z = blockIdx.z;
    const __nv_bfloat16* A = ga.A[z];
    const __nv_bfloat16* B = ga.B[z];
    const float* bias = ga.bias[z];
    __nv_bfloat16* C = ga.C[z];

    extern __shared__ char smx[];
    __nv_bfloat16* Bs = (__nv_bfloat16*)smx;
    __nv_bfloat16* Abuf0 = (__nv_bfloat16*)(smx + SMB);
    __nv_bfloat16* Abuf1 = (__nv_bfloat16*)(smx + 2 * SMB);

    int tid = threadIdx.x;
    int warp = tid >> 5;
    int row0 = (warp >> 1) * 32;
    int col0 = (warp & 1) * 64;
    int bn = blockIdx.x * 128;

    int mt = blockIdx.y;
    if (mt >= mtiles) return;

    tile_load_async(Bs, B + (size_t)bn * 128, tid);
    tile_load_async(Abuf0, A + (size_t)mt * 128 * 128, tid);
    asm volatile("cp.async.commit_group;");

    int buf = 0;
    while (mt < mtiles) {
        int nxt = mt + gridDim.y;
        bool pf = (nxt < mtiles);
        __nv_bfloat16* Acur = buf ? Abuf1 : Abuf0;
        __nv_bfloat16* Aalt = buf ? Abuf0 : Abuf1;
        if (pf) {
            tile_load_async(Aalt, A + (size_t)nxt * 128 * 128, tid);
            asm volatile("cp.async.commit_group;");
            asm volatile("cp.async.wait_group 1;");
        } else {
            asm volatile("cp.async.wait_group 0;");
        }
        __syncthreads();

        wmma::fragment<wmma::accumulator, 16, 16, 16, float> acc[2][4];
#pragma unroll
        for (int i = 0; i < 2; i++)
#pragma unroll
            for (int j = 0; j < 4; j++) wmma::fill_fragment(acc[i][j], 0.0f);

#pragma unroll
        for (int k = 0; k < 8; k++) {
            wmma::fragment<wmma::matrix_a, 16, 16, 16, __nv_bfloat16, wmma::row_major> a[2];
            wmma::fragment<wmma::matrix_b, 16, 16, 16, __nv_bfloat16, wmma::col_major> b[4];
#pragma unroll
            for (int i = 0; i < 2; i++)
                wmma::load_matrix_sync(a[i], Acur + (row0 + i * 16) * LDTB + k * 16, LDTB);
#pragma unroll
            for (int j = 0; j < 4; j++)
                wmma::load_matrix_sync(b[j], Bs + (col0 + j * 16) * LDTB + k * 16, LDTB);
#pragma unroll
            for (int i = 0; i < 2; i++)
#pragma unroll
                for (int j = 0; j < 4; j++)
                    wmma::mma_sync(acc[i][j], a[i], b[j], acc[i][j]);
        }
        __syncthreads();

        float* Cs = (float*)Acur;
        int bm = mt * 128;
#pragma unroll
        for (int h = 0; h < 2; h++) {
            if ((warp >> 2) == h) {
                int lr = row0 - h * 64;
#pragma unroll
                for (int i = 0; i < 2; i++)
#pragma unroll
                    for (int j = 0; j < 4; j++)
                        wmma::store_matrix_sync(Cs + (lr + i * 16) * LDC2 + col0 + j * 16,
                                                acc[i][j], LDC2, wmma::mem_row_major);
            }
            __syncthreads();
            for (int slot = tid; slot < 64 * 32; slot += 256) {
                int r = slot >> 5;
                int c4 = (slot & 31) * 4;
                float4 v = *(float4*)(Cs + r * LDC2 + c4);
                if (bias != nullptr) {
                    v.x += bias[bn + c4 + 0];
                    v.y += bias[bn + c4 + 1];
                    v.z += bias[bn + c4 + 2];
                    v.w += bias[bn + c4 + 3];
                }
                int grow = bm + h * 64 + r;
                __nv_bfloat16* crow = C + (size_t)grow * J + bn + c4;
                *(__nv_bfloat162*)(crow)     = __floats2bfloat162_rn(v.x, v.y);
                *(__nv_bfloat162*)(crow + 2) = __floats2bfloat162_rn(v.z, v.w);
            }
            __syncthreads();
        }
        mt = nxt;
        buf ^= 1;
    }
}

// ---------------- GRU math ----------------
__device__ __forceinline__ float tanhapx(float x) {
    float y;
    asm("tanh.approx.f32 %0, %1;" : "=f"(y) : "f"(x));
    return y;
}
__device__ __forceinline__ float sigf(float x) {
    return 0.5f * tanhapx(0.5f * x) + 0.5f;
}
__device__ __forceinline__ float4 ldbf4(const __nv_bfloat16* p) {
    uint2 u = *(const uint2*)p;
    __nv_bfloat162 a = *(__nv_bfloat162*)&u.x;
    __nv_bfloat162 b = *(__nv_bfloat162*)&u.y;
    float2 fa = __bfloat1622float2(a), fb = __bfloat1622float2(b);
    return make_float4(fa.x, fa.y, fb.x, fb.y);
}
__device__ __forceinline__ void stbf4(__nv_bfloat16* p, float4 v) {
    uint2 u;
    *(__nv_bfloat162*)&u.x = __floats2bfloat162_rn(v.x, v.y);
    *(__nv_bfloat162*)&u.y = __floats2bfloat162_rn(v.z, v.w);
    *(uint2*)p = u;
}
__device__ __forceinline__ float4 gru4(float4 ir, float4 iz, float4 in4,
                                       float4 hr, float4 hz, float4 hn, float4 h) {
    float4 o;
    { float r = sigf(ir.x + hr.x), z = sigf(iz.x + hz.x);
      float nn = tanhapx(in4.x + r * hn.x); o.x = (1.f - z) * nn + z * h.x; }
    { float r = sigf(ir.y + hr.y), z = sigf(iz.y + hz.y);
      float nn = tanhapx(in4.y + r * hn.y); o.y = (1.f - z) * nn + z * h.y; }
    { float r = sigf(ir.z + hr.z), z = sigf(iz.z + hz.z);
      float nn = tanhapx(in4.z + r * hn.z); o.z = (1.f - z) * nn + z * h.z; }
    { float r = sigf(ir.w + hr.w), z = sigf(iz.w + hz.w);
      float nn = tanhapx(in4.w + r * hn.w); o.w = (1.f - z) * nn + z * h.w; }
    return o;
}

// i=0: hb3[s] = GRU(gi3[s], gh3[s], hold=xb)   (blockIdx.y = s)
__global__ void gru3_first_kernel(const __nv_bfloat16* __restrict__ gi3,
                                  const __nv_bfloat16* __restrict__ gh3,
                                  const __nv_bfloat16* __restrict__ xb,
                                  __nv_bfloat16* __restrict__ hb3) {
    int idx = blockIdx.x * blockDim.x + threadIdx.x;
    if (idx >= NN * 32) return;
    int s = blockIdx.y;
    int n = idx >> 5;
    int c = (idx & 31) * 4;
    const __nv_bfloat16* gir = gi3 + (size_t)s * NP * 384 + (size_t)n * 384;
    const __nv_bfloat16* ghr = gh3 + (size_t)s * NP * 384 + (size_t)n * 384;
    float4 h = ldbf4(xb + (size_t)n * 128 + c);
    float4 o = gru4(ldbf4(gir + c), ldbf4(gir + 128 + c), ldbf4(gir + 256 + c),
                    ldbf4(ghr + c), ldbf4(ghr + 128 + c), ldbf4(ghr + 256 + c), h);
    stbf4(hb3 + (size_t)s * NP * 128 + (size_t)n * 128 + c, o);
}

// i=1: x = mean_s GRU(gi3[s], gh3[s], hold=hb3[s]) -> xp (f32) + xb (bf16)
__global__ void gru3_final_kernel(const __nv_bfloat16* __restrict__ gi3,
                                  const __nv_bfloat16* __restrict__ gh3,
                                  const __nv_bfloat16* __restrict__ hb3,
                                  float* __restrict__ xp,
                                  __nv_bfloat16* __restrict__ xb) {
    int idx = blockIdx.x * blockDim.x + threadIdx.x;
    if (idx >= NN * 32) return;
    int n = idx >> 5;
    int c = (idx & 31) * 4;
    float4 xv = make_float4(0.f, 0.f, 0.f, 0.f);
#pragma unroll
    for (int s = 0; s < SS; s++) {
        const __nv_bfloat16* gir = gi3 + (size_t)s * NP * 384 + (size_t)n * 384;
        const __nv_bfloat16* ghr = gh3 + (size_t)s * NP * 384 + (size_t)n * 384;
        float4 h = ldbf4(hb3 + (size_t)s * NP * 128 + (size_t)n * 128 + c);
        float4 o = gru4(ldbf4(gir + c), ldbf4(gir + 128 + c), ldbf4(gir + 256 + c),
                        ldbf4(ghr + c), ldbf4(ghr + 128 + c), ldbf4(ghr + 256 + c), h);
        xv.x += o.x; xv.y += o.y; xv.z += o.z; xv.w += o.w;
    }
    xv.x *= (1.0f / 3.0f); xv.y *= (1.0f / 3.0f);
    xv.z *= (1.0f / 3.0f); xv.w *= (1.0f / 3.0f);
    size_t p = (size_t)n * 128 + c;
    *(float4*)(xp + p) = xv;
    stbf4(xb + p, xv);
}

// ---------------- pooling / MLP ----------------
__global__ void cnt_kernel(const int* __restrict__ batch, float* __restrict__ cnt, int n) {
    int i = blockIdx.x * blockDim.x + threadIdx.x;
    if (i < n) atomicAdd(&cnt[batch[i]], 1.0f);
}
__global__ void pool_kernel(const float* __restrict__ x, const int* __restrict__ batch,
                            float* __restrict__ pool) {
    int idx = blockIdx.x * blockDim.x + threadIdx.x;
    if (idx >= NN * 32) return;
    int n = idx >> 5;
    int c = (idx & 31) * 4;
    int g = batch[n];
    float4 v = *(const float4*)(x + (size_t)n * 128 + c);
    float* o = pool + (size_t)g * 128 + c;
    asm volatile("red.global.add.v4.f32 [%0], {%1,%2,%3,%4};"
                 :: "l"(o), "f"(v.x), "f"(v.y), "f"(v.z), "f"(v.w) : "memory");
}
__global__ void mlp_kernel(const float* __restrict__ pool, const float* __restrict__ cnt,
                           const float* __restrict__ pt,
                           const float* __restrict__ fc1w, const float* __restrict__ fc1b,
                           const float* __restrict__ fc2w, const float* __restrict__ fc2b,
                           const float* __restrict__ fclw, const float* __restrict__ fclb,
                           float* __restrict__ out) {
    __shared__ float h1[GG * 80];
    __shared__ float h2[GG * 80];
    int tid = threadIdx.x;
    for (int t = tid; t < GG * 80; t += blockDim.x) {
        int g = t / 80, j = t - (t / 80) * 80;
        float ic = 1.0f / fmaxf(cnt[g], 1.0f);
        float acc = fc1b[j];
        const float* w = fc1w + j * 129;
        const float* p = pool + g * 128;
        for (int k = 0; k < 128; k++) acc = fmaf(p[k] * ic, w[k], acc);
        acc = fmaf(pt[g], w[128], acc);
        h1[t] = acc > 0.f ? acc : 0.01f * acc;
    }
    __syncthreads();
    for (int t = tid; t < GG * 80; t += blockDim.x) {
        int g = t / 80, j = t - (t / 80) * 80;
        float acc = fc2b[j];
        const float* w = fc2w + j * 80;
        const float* hh = h1 + g * 80;
        for (int k = 0; k < 80; k++) acc = fmaf(hh[k], w[k], acc);
        h2[t] = acc > 0.f ? acc : 0.01f * acc;
    }
    __syncthreads();
    for (int t = tid; t < GG * OUTD; t += blockDim.x) {
        int g = t / OUTD, o = t - (t / OUTD) * OUTD;
        float acc = fclb[o];
        const float* w = fclw + o * 80;
        const float* hh = h2 + g * 80;
        for (int k = 0; k < 80; k++) acc = fmaf(hh[k], w[k], acc);
        out[t] = acc;
    }
}

// ---------------- host launcher ----------------
extern "C" void kernel_launch(void* const* d_in, const int* in_sizes, int n_in,
                              void* d_out, int out_size) {
    (void)in_sizes; (void)n_in; (void)out_size;
    const float* x     = (const float*)d_in[0];
    const int*   eidx  = (const int*)d_in[1];
    const int*   eattr = (const int*)d_in[2];
    const int*   batch = (const int*)d_in[3];
    const float* pt    = (const float*)d_in[4];
    const float* W     = (const float*)d_in[5];
    const float* wih   = (const float*)d_in[6];
    const float* whh   = (const float*)d_in[7];
    const float* bih   = (const float*)d_in[8];
    const float* bhh   = (const float*)d_in[9];
    const float* fc1w  = (const float*)d_in[10];
    const float* fc1b  = (const float*)d_in[11];
    const float* fc2w  = (const float*)d_in[12];
    const float* fc2b  = (const float*)d_in[13];
    const float* fclw  = (const float*)d_in[14];
    const float* fclb  = (const float*)d_in[15];
    float* out = (float*)d_out;

    const int* src = eidx;
    const int* dst = eidx + EE;

    float *xp, *poolp, *cntp;
    __nv_bfloat16 *xb, *hb3, *agg3, *gi3, *gh3, *wcb, *wihb, *whhb, *Wb;
    int *bsrcp, *ecntp, *ecurp, *eoffp;
    cudaGetSymbolAddress((void**)&xp,    g_x);
    cudaGetSymbolAddress((void**)&xb,    g_xb);
    cudaGetSymbolAddress((void**)&hb3,   g_hb3);
    cudaGetSymbolAddress((void**)&agg3,  g_agg3);
    cudaGetSymbolAddress((void**)&gi3,   g_gi3);
    cudaGetSymbolAddress((void**)&gh3,   g_gh3);
    cudaGetSymbolAddress((void**)&wcb,   g_wcb);
    cudaGetSymbolAddress((void**)&wihb,  g_wihb);
    cudaGetSymbolAddress((void**)&whhb,  g_whhb);
    cudaGetSymbolAddress((void**)&Wb,    g_Wb);
    cudaGetSymbolAddress((void**)&poolp, g_pool);
    cudaGetSymbolAddress((void**)&cntp,  g_cnt);
    cudaGetSymbolAddress((void**)&bsrcp, g_bsrc);
    cudaGetSymbolAddress((void**)&ecntp, g_ecnt);
    cudaGetSymbolAddress((void**)&ecurp, g_ecur);
    cudaGetSymbolAddress((void**)&eoffp, g_eoff);

    cudaFuncSetAttribute(bf16_gemm, cudaFuncAttributeMaxDynamicSharedMemorySize, BG_SMEM);

    const int TB = 256;

    // preprocessing
    copy_pad_kernel<<<(NP * 32 + TB - 1) / TB, TB>>>(x, xp, xb);
    cvt_bf16_kernel<<<(SS * 384 * 32 + TB - 1) / TB, TB>>>(whh, whhb, SS * 384 * 32);
    cvt_bf16_kernel<<<(SS * 384 * 32 + TB - 1) / TB, TB>>>(wih, wihb, SS * 384 * 32);
    cvt_bf16_kernel<<<(SS * 2 * 128 * 32 + TB - 1) / TB, TB>>>(W, Wb, SS * 2 * 128 * 32);
    zero2_ints<<<(NPS + TB - 1) / TB, TB>>>(ecntp, ecurp, NPS);
    ecount_kernel<<<(EE + TB - 1) / TB, TB>>>(dst, eattr, ecntp, EE);
    scan_kernel<<<1, 1024>>>(ecntp, eoffp, NPS);
    fill_kernel<<<(EE + TB - 1) / TB, TB>>>(src, dst, eattr, eoffp, ecurp, bsrcp, EE);

    // combined weights Wc[s,i] = wih[s] @ W[s,i]^T : one z=6 batch
    {
        GemmArgs ga;
        for (int z = 0; z < 6; z++) {
            int s = z / 2, i = z % 2;
            ga.A[z] = wihb + (size_t)s * 384 * 128;
            ga.B[z] = Wb + (size_t)(s * 2 + i) * 128 * 128;
            ga.bias[z] = nullptr;
            ga.C[z] = wcb + (size_t)(s * 2 + i) * 384 * 128;
        }
        bf16_gemm<<<dim3(1, 3, 6), TB, BG_SMEM>>>(ga, 128, 3);
    }

    // main loop: per pass, two super-steps (i=0, i=1); edge sets batched in z
    for (int pass = 0; pass < 2; pass++) {
        // ---- i = 0 ----
        {
            Feat3 f; f.p[0] = xb; f.p[1] = xb; f.p[2] = xb;
            gather3_kernel<<<(SS * NP * 32 + TB - 1) / TB, TB>>>(eoffp, bsrcp, f, agg3);
            GemmArgs ga;
            for (int s = 0; s < SS; s++) {
                ga.A[s] = xb;
                ga.B[s] = whhb + (size_t)s * 384 * 128;
                ga.bias[s] = bhh + s * 384;
                ga.C[s] = gh3 + (size_t)s * NP * 384;
                ga.A[3 + s] = agg3 + (size_t)s * NP * 128;
                ga.B[3 + s] = wcb + (size_t)(s * 2 + 0) * 384 * 128;
                ga.bias[3 + s] = bih + s * 384;
                ga.C[3 + s] = gi3 + (size_t)s * NP * 384;
            }
            bf16_gemm<<<dim3(3, 16, 6), TB, BG_SMEM>>>(ga, 384, M_TILES);
            gru3_first_kernel<<<dim3((NN * 32 + TB - 1) / TB, 3), TB>>>(gi3, gh3, xb, hb3);
        }
        // ---- i = 1 ----
        {
            Feat3 f;
            f.p[0] = hb3;
            f.p[1] = hb3 + (size_t)NP * 128;
            f.p[2] = hb3 + (size_t)2 * NP * 128;
            gather3_kernel<<<(SS * NP * 32 + TB - 1) / TB, TB>>>(eoffp, bsrcp, f, agg3);
            GemmArgs ga;
            for (int s = 0; s < SS; s++) {
                ga.A[s] = hb3 + (size_t)s * NP * 128;
                ga.B[s] = whhb + (size_t)s * 384 * 128;
                ga.bias[s] = bhh + s * 384;
                ga.C[s] = gh3 + (size_t)s * NP * 384;
                ga.A[3 + s] = agg3 + (size_t)s * NP * 128;
                ga.B[3 + s] = wcb + (size_t)(s * 2 + 1) * 384 * 128;
                ga.bias[3 + s] = bih + s * 384;
                ga.C[3 + s] = gi3 + (size_t)s * NP * 384;
            }
            bf16_gemm<<<dim3(3, 16, 6), TB, BG_SMEM>>>(ga, 384, M_TILES);
            gru3_final_kernel<<<(NN * 32 + TB - 1) / TB, TB>>>(gi3, gh3, hb3, xp, xb);
        }
    }

    // pooling + MLP
    zero_kernel<<<(GG * DD / 4 + TB - 1) / TB, TB>>>(poolp, GG * DD / 4);
    zero_kernel<<<1, GG / 4>>>(cntp, GG / 4);
    cnt_kernel<<<(NN + TB - 1) / TB, TB>>>(batch, cntp, NN);
    pool_kernel<<<(NN * 32 + TB - 1) / TB, TB>>>(xp, batch, poolp);
    mlp_kernel<<<1, 256>>>(poolp, cntp, pt, fc1w, fc1b, fc2w, fc2b, fclw, fclb, out);
}